// round 1
// baseline (speedup 1.0000x reference)
#include <cuda_runtime.h>
#include <math.h>

#define SS 256
#define BB 256
#define HH 1024
#define LL 3
#define NCTA 128
#define NTHR 256
#define TM 32
#define TN 128
#define KT 16
#define NK (HH / KT)
#define NTILES 64

// Scratch state (device globals: no allocation allowed)
__device__ float g_h[LL][2][BB * HH];     // double-buffered hidden state per layer
__device__ float g_part[BB * HH];         // ih-partial per stage (tiles disjoint)
__device__ unsigned g_sync[8 + NTILES];   // [0]=barrier count, [1]=barrier gen, [8..]=per-tile flags

// Sense-free grid barrier: monotonically increasing generation, count resets itself.
// All 128 CTAs are co-resident (128 <= 148 SMs, 1 CTA/SM), so spinning is safe.
__device__ __forceinline__ void grid_barrier(unsigned target) {
    __syncthreads();
    __threadfence();   // release: drain this thread's stores to L2 (and IVALL on sm_103a)
    if (threadIdx.x == 0) {
        unsigned old = atomicAdd(&g_sync[0], 1u);
        if (old == NCTA - 1) {
            atomicExch(&g_sync[0], 0u);   // reset BEFORE releasing others
            __threadfence();
            atomicExch(&g_sync[1], target);
        } else {
            while (*((volatile unsigned*)&g_sync[1]) < target) { }
        }
        __threadfence(); // acquire: invalidate L1 so subsequent loads see fresh data
    }
    __syncthreads();
}

__global__ __launch_bounds__(NTHR) void rnn_persistent(
    const float* __restrict__ x,
    const float* __restrict__ h0,
    const float* __restrict__ W_ih,
    const float* __restrict__ W_hh,
    const float* __restrict__ b_ih,
    const float* __restrict__ b_hh,
    float* __restrict__ out)
{
    const int tid  = threadIdx.x;
    const int cta  = blockIdx.x;
    const int tile = cta >> 1;     // 64 tiles: 8 M-tiles x 8 N-tiles
    const int half = cta & 1;      // 0: inp @ W_ih^T   1: h_prev @ W_hh^T
    const int m0 = (tile & 7) * TM;
    const int n0 = (tile >> 3) * TN;

    // global->smem staging assignments
    const int am = tid >> 3;        // 0..31  (A row within tile)
    const int ak = (tid & 7) * 2;   // 0..14  (A k, float2)
    const int bn = tid >> 1;        // 0..127 (W row within tile)
    const int bk = (tid & 1) * 8;   // 0 or 8 (W k, 2x float4)
    // compute fragment assignment: warp -> 4 rows, lane -> 4 cols
    const int r0 = (tid >> 5) * 4;
    const int c0 = (tid & 31) * 4;

    __shared__ __align__(16) float As[KT][36];   // [k][m], padded
    __shared__ __align__(16) float Bs[KT][TN];   // [k][n]

    // init hidden state (parity 1 is read at t=0) from h_0
    for (int i = cta * NTHR + tid; i < LL * BB * HH; i += NCTA * NTHR) {
        int l = i / (BB * HH);
        g_h[l][1][i - l * (BB * HH)] = h0[i];
    }
    unsigned bt = 1;
    grid_barrier(bt++);

    for (int t = 0; t < SS; t++) {
        const int pb = t & 1;   // write parity this step; read parity pb^1
        for (int l = 0; l < LL; l++) {
            const int gs = t * 3 + l;   // global stage index

            const float* Aptr;
            const float* Wptr;
            if (half == 0) {
                Aptr = (l == 0) ? (x + (size_t)t * BB * HH) : g_h[l - 1][pb];
                Wptr = W_ih + (size_t)l * HH * HH;
            } else {
                Aptr = g_h[l][pb ^ 1];
                Wptr = W_hh + (size_t)l * HH * HH;
            }
            const float* Arow = Aptr + (size_t)(m0 + am) * HH + ak;
            const float* Wrow = Wptr + (size_t)(n0 + bn) * HH + bk;

            float acc[4][4];
            #pragma unroll
            for (int i = 0; i < 4; i++)
                #pragma unroll
                for (int j = 0; j < 4; j++) acc[i][j] = 0.f;

            // software-pipelined K loop: prefetch next chunk into regs during compute
            float2 ar  = *(const float2*)(Arow);
            float4 br0 = *(const float4*)(Wrow);
            float4 br1 = *(const float4*)(Wrow + 4);

            for (int kc = 0; kc < NK; kc++) {
                __syncthreads();
                As[ak][am]     = ar.x;
                As[ak + 1][am] = ar.y;
                Bs[bk + 0][bn] = br0.x;
                Bs[bk + 1][bn] = br0.y;
                Bs[bk + 2][bn] = br0.z;
                Bs[bk + 3][bn] = br0.w;
                Bs[bk + 4][bn] = br1.x;
                Bs[bk + 5][bn] = br1.y;
                Bs[bk + 6][bn] = br1.z;
                Bs[bk + 7][bn] = br1.w;
                __syncthreads();
                if (kc + 1 < NK) {
                    const int kb = (kc + 1) * KT;
                    ar  = *(const float2*)(Arow + kb);
                    br0 = *(const float4*)(Wrow + kb);
                    br1 = *(const float4*)(Wrow + kb + 4);
                }
                #pragma unroll
                for (int kk = 0; kk < KT; kk++) {
                    float4 a = *(const float4*)&As[kk][r0];  // broadcast within warp
                    float4 b = *(const float4*)&Bs[kk][c0];  // conflict-free
                    float av[4] = {a.x, a.y, a.z, a.w};
                    float bv[4] = {b.x, b.y, b.z, b.w};
                    #pragma unroll
                    for (int i = 0; i < 4; i++)
                        #pragma unroll
                        for (int j = 0; j < 4; j++)
                            acc[i][j] += av[i] * bv[j];
                }
            }

            if (half == 0) {
                // publish ih-partial, raise per-tile flag
                #pragma unroll
                for (int i = 0; i < 4; i++) {
                    float4 v = make_float4(acc[i][0], acc[i][1], acc[i][2], acc[i][3]);
                    *(float4*)&g_part[(size_t)(m0 + r0 + i) * HH + n0 + c0] = v;
                }
                __threadfence();     // release (per-thread: drain STGs)
                __syncthreads();
                if (tid == 0) atomicAdd(&g_sync[8 + tile], 1u);
            } else {
                // wait for ih-partial, combine + bias + tanh, write h (and y for l==2)
                if (tid == 0) {
                    while (*((volatile unsigned*)&g_sync[8 + tile]) < (unsigned)(gs + 1)) { }
                }
                __syncthreads();
                __threadfence();     // acquire: L1 invalidate before reading g_part
                const float4 bi = *(const float4*)&b_ih[l * HH + n0 + c0];
                const float4 bh = *(const float4*)&b_hh[l * HH + n0 + c0];
                float* hdst = g_h[l][pb];
                #pragma unroll
                for (int i = 0; i < 4; i++) {
                    const size_t off = (size_t)(m0 + r0 + i) * HH + n0 + c0;
                    float4 pv = *(const float4*)&g_part[off];
                    float4 o;
                    o.x = tanhf(acc[i][0] + pv.x + bi.x + bh.x);
                    o.y = tanhf(acc[i][1] + pv.y + bi.y + bh.y);
                    o.z = tanhf(acc[i][2] + pv.z + bi.z + bh.z);
                    o.w = tanhf(acc[i][3] + pv.w + bi.w + bh.w);
                    *(float4*)&hdst[off] = o;
                    if (l == LL - 1) {
                        *(float4*)&out[(size_t)t * BB * HH + off] = o;
                    }
                }
            }
            grid_barrier(bt++);   // entry fence publishes h writes
        }
    }

    // h_N: final states live in parity (SS-1)&1 == 1
    const size_t yoff = (size_t)SS * BB * HH;
    for (int i = cta * NTHR + tid; i < LL * BB * HH; i += NCTA * NTHR) {
        int l = i / (BB * HH);
        out[yoff + i] = g_h[l][1][i - l * (BB * HH)];
    }
}

extern "C" void kernel_launch(void* const* d_in, const int* in_sizes, int n_in,
                              void* d_out, int out_size) {
    const float* x    = (const float*)d_in[0];
    const float* h0   = (const float*)d_in[1];
    const float* W_ih = (const float*)d_in[2];
    const float* W_hh = (const float*)d_in[3];
    const float* b_ih = (const float*)d_in[4];
    const float* b_hh = (const float*)d_in[5];
    float* out = (float*)d_out;

    // reset barrier/flag state every (graph-replayed) launch
    void* sp = nullptr;
    cudaGetSymbolAddress(&sp, g_sync);
    cudaMemsetAsync(sp, 0, sizeof(unsigned) * (8 + NTILES));

    rnn_persistent<<<NCTA, NTHR>>>(x, h0, W_ih, W_hh, b_ih, b_hh, out);
}

// round 4
// speedup vs baseline: 2.7099x; 2.7099x over previous
#include <cuda_runtime.h>
#include <cuda_bf16.h>
#include <stdint.h>
#include <math.h>

#define SS 256
#define BB 256
#define HH 1024
#define LL 3
#define NCTA 96
#define NTHR 256
#define KC 64
#define NCHUNK 32
#define BH (BB*HH)
#define GSTRIDE (NCTA*NTHR)
#define KTOT 2048
// SMEM buffer layout (bytes, per buffer): Ah[128][72] Al[128][72] Wh[64][72] Wl[64][72]
#define RSB 144              /* row stride bytes (72 halves) */
#define OFF_AL 18432
#define OFF_WH 36864
#define OFF_WL 46080
#define BUFSZ 55296
#define SMEM_DYN (2*BUFSZ + 16)

typedef unsigned short ush;

// ---------------- device state (static scratch; allocation forbidden) --------
__device__ ush g_h_hi[LL][2][BH];
__device__ ush g_h_lo[LL][2][BH];
__device__ ush g_x_hi[2][BH];
__device__ ush g_x_lo[2][BH];
__device__ ush g_w_hi[LL][HH][KTOT];   // [l][n][k2]: k2<1024 -> W_ih, else W_hh
__device__ ush g_w_lo[LL][HH][KTOT];
__device__ unsigned g_sync[2];

// ---------------- helpers ----------------------------------------------------
static __device__ __forceinline__ unsigned smem_u32(const void* p) {
    unsigned a;
    asm("{ .reg .u64 t; cvta.to.shared.u64 t, %1; cvt.u32.u64 %0, t; }" : "=r"(a) : "l"(p));
    return a;
}
static __device__ __forceinline__ ush f2bf(float f) {
    ush r; asm("cvt.rn.bf16.f32 %0, %1;" : "=h"(r) : "f"(f)); return r;
}
static __device__ __forceinline__ void split2(float f, ush& hi, ush& lo) {
    unsigned u = __float_as_uint(f) & 0xFFFF0000u;
    hi = (ush)(u >> 16);
    lo = f2bf(f - __uint_as_float(u));
}
static __device__ __forceinline__ void cp16(unsigned s, const void* g) {
    asm volatile("cp.async.cg.shared.global [%0], [%1], 16;" :: "r"(s), "l"(g) : "memory");
}
static __device__ __forceinline__ void cp_commit() {
    asm volatile("cp.async.commit_group;" ::: "memory");
}
static __device__ __forceinline__ void cp_wait1() {
    asm volatile("cp.async.wait_group 1;" ::: "memory");
}
static __device__ __forceinline__ void cp_wait0() {
    asm volatile("cp.async.wait_group 0;" ::: "memory");
}
static __device__ __forceinline__ void ldm_x4(unsigned* r, unsigned a) {
    asm volatile("ldmatrix.sync.aligned.m8n8.x4.shared.b16 {%0,%1,%2,%3}, [%4];"
                 : "=r"(r[0]), "=r"(r[1]), "=r"(r[2]), "=r"(r[3]) : "r"(a));
}
static __device__ __forceinline__ void mma16816(float* c, const unsigned* a, const unsigned* b) {
    asm volatile("mma.sync.aligned.m16n8k16.row.col.f32.bf16.bf16.f32 "
                 "{%0,%1,%2,%3}, {%4,%5,%6,%7}, {%8,%9}, {%0,%1,%2,%3};"
                 : "+f"(c[0]), "+f"(c[1]), "+f"(c[2]), "+f"(c[3])
                 : "r"(a[0]), "r"(a[1]), "r"(a[2]), "r"(a[3]), "r"(b[0]), "r"(b[1]));
}

// sense-free grid barrier; all NCTA CTAs co-resident (96 <= 148 SMs)
__device__ __forceinline__ void grid_barrier(unsigned target) {
    __syncthreads();
    __threadfence();
    if (threadIdx.x == 0) {
        unsigned old = atomicAdd(&g_sync[0], 1u);
        if (old == NCTA - 1) {
            atomicExch(&g_sync[0], 0u);
            __threadfence();
            atomicExch(&g_sync[1], target);
        } else {
            while (*((volatile unsigned*)&g_sync[1]) < target) { }
        }
        __threadfence();
    }
    __syncthreads();
}

// issue cp.async loads for chunk c into buffer at sbase (12 x 16B per thread)
static __device__ __forceinline__ void issue_loads(
    int c, unsigned sbase, int tid, int m0,
    const ush* inpHi, const ush* inpLo, const ush* prvHi, const ush* prvLo,
    const ush* wHi, const ush* wLo)
{
    const int ko = (c & 15) * KC;
    const ush* aHi = (c < 16) ? inpHi : prvHi;
    const ush* aLo = (c < 16) ? inpLo : prvLo;
    #pragma unroll
    for (int j = 0; j < 4; j++) {                 // A_hi: 1024 chunks
        int cid = tid + 256 * j;
        int row = cid >> 3, seg = cid & 7;
        cp16(sbase + row * RSB + seg * 16, aHi + (size_t)(m0 + row) * HH + ko + seg * 8);
    }
    #pragma unroll
    for (int j = 0; j < 4; j++) {                 // A_lo
        int cid = tid + 256 * j;
        int row = cid >> 3, seg = cid & 7;
        cp16(sbase + OFF_AL + row * RSB + seg * 16, aLo + (size_t)(m0 + row) * HH + ko + seg * 8);
    }
    #pragma unroll
    for (int j = 0; j < 2; j++) {                 // W_hi: 512 chunks
        int cid = tid + 256 * j;
        int row = cid >> 3, seg = cid & 7;
        cp16(sbase + OFF_WH + row * RSB + seg * 16, wHi + (size_t)row * KTOT + c * KC + seg * 8);
    }
    #pragma unroll
    for (int j = 0; j < 2; j++) {                 // W_lo
        int cid = tid + 256 * j;
        int row = cid >> 3, seg = cid & 7;
        cp16(sbase + OFF_WL + row * RSB + seg * 16, wLo + (size_t)row * KTOT + c * KC + seg * 8);
    }
}

// warp-level compute on one ready chunk buffer
static __device__ __forceinline__ void compute_chunk(
    unsigned sbase, int lane, int wm, int wn, float acc[2][4][4])
{
    // shared lane->address pattern for both A (m16xk16) and B (n16xk16) tiles:
    // lanes 0-7: rows 0-7 @ k+0 | 8-15: rows 8-15 @ k+0 | 16-23: rows 0-7 @ k+8 | 24-31: rows 8-15 @ k+8
    const int arow = lane & 15, akoff = (lane >> 4) * 8;
    #pragma unroll
    for (int kk = 0; kk < 4; kk++) {
        unsigned ah[2][4], al[2][4], bh[4][2], bl[4][2];
        #pragma unroll
        for (int mb = 0; mb < 2; mb++) {
            unsigned addr = sbase + (wm + mb * 16 + arow) * RSB + (kk * 16 + akoff) * 2;
            ldm_x4(ah[mb], addr);
            ldm_x4(al[mb], addr + OFF_AL);
        }
        #pragma unroll
        for (int g = 0; g < 2; g++) {
            // non-trans ldmatrix on W[n][k] yields the col-major B fragment directly:
            // r0 = n-block0 k-lo, r1 = n-block1 k-lo, r2 = n-block0 k-hi, r3 = n-block1 k-hi
            unsigned addr = sbase + OFF_WH + (wn + g * 16 + arow) * RSB + (kk * 16 + akoff) * 2;
            unsigned r[4];
            ldm_x4(r, addr);
            bh[2 * g][0] = r[0]; bh[2 * g][1] = r[2];
            bh[2 * g + 1][0] = r[1]; bh[2 * g + 1][1] = r[3];
            ldm_x4(r, addr + (OFF_WL - OFF_WH));
            bl[2 * g][0] = r[0]; bl[2 * g][1] = r[2];
            bl[2 * g + 1][0] = r[1]; bl[2 * g + 1][1] = r[3];
        }
        #pragma unroll
        for (int mb = 0; mb < 2; mb++)
            #pragma unroll
            for (int nb = 0; nb < 4; nb++) {
                mma16816(acc[mb][nb], ah[mb], bh[nb]);
                mma16816(acc[mb][nb], ah[mb], bl[nb]);
                mma16816(acc[mb][nb], al[mb], bh[nb]);
            }
    }
}

// ---------------- persistent kernel ------------------------------------------
__global__ void __launch_bounds__(NTHR, 1) rnn_mma(
    const float* __restrict__ x, const float* __restrict__ h0,
    const float* __restrict__ W_ih, const float* __restrict__ W_hh,
    const float* __restrict__ b_ih, const float* __restrict__ b_hh,
    float* __restrict__ out)
{
    extern __shared__ __align__(16) char dsm[];
    __shared__ float s_bias[64];

    const int tid = threadIdx.x;
    const int lane = tid & 31;
    const int w = tid >> 5;
    const int wm = (w >> 1) * 32;        // warp m-offset in tile
    const int wn = (w & 1) * 32;         // warp n-offset in tile
    const int cta = blockIdx.x;
    const int l = cta / 32;              // layer group
    const int id = cta % 32;
    const int m0 = (id & 1) * 128;
    const int n0 = (id >> 1) * 64;

    const unsigned dynu = smem_u32(dsm);

    if (tid < 64) s_bias[tid] = b_ih[l * HH + n0 + tid] + b_hh[l * HH + n0 + tid];

    // ---- prepass: split W (ih||hh packed), h0 (parity 1), x_0 (slot 0) ------
    for (int idx = cta * NTHR + tid; idx < LL * HH * KTOT; idx += GSTRIDE) {
        int l2 = idx >> 21;
        int rem = idx & ((1 << 21) - 1);
        int n = rem >> 11;
        int k2 = rem & (KTOT - 1);
        float f = (k2 < HH) ? W_ih[((size_t)l2 * HH + n) * HH + k2]
                            : W_hh[((size_t)l2 * HH + n) * HH + (k2 - HH)];
        split2(f, ((ush*)g_w_hi)[idx], ((ush*)g_w_lo)[idx]);
    }
    for (int idx = cta * NTHR + tid; idx < LL * BH; idx += GSTRIDE) {
        int l2 = idx >> 18;
        int i = idx & (BH - 1);
        split2(h0[idx], g_h_hi[l2][1][i], g_h_lo[l2][1][i]);
    }
    for (int idx = cta * NTHR + tid; idx < BH; idx += GSTRIDE)
        split2(x[idx], g_x_hi[0][idx], g_x_lo[0][idx]);

    grid_barrier(1u);
    unsigned bt = 2;

    for (int d = 0; d < SS + LL - 1; d++) {
        const int t = d - l;
        if (t >= 0 && t < SS) {
            const ush* inpHi = (l == 0) ? g_x_hi[t & 1] : g_h_hi[l - 1][t & 1];
            const ush* inpLo = (l == 0) ? g_x_lo[t & 1] : g_h_lo[l - 1][t & 1];
            const ush* prvHi = g_h_hi[l][(t & 1) ^ 1];
            const ush* prvLo = g_h_lo[l][(t & 1) ^ 1];
            const ush* wHi = &g_w_hi[l][n0][0];
            const ush* wLo = &g_w_lo[l][n0][0];

            float acc[2][4][4];
            #pragma unroll
            for (int a = 0; a < 2; a++)
                #pragma unroll
                for (int b = 0; b < 4; b++)
                    #pragma unroll
                    for (int cc = 0; cc < 4; cc++) acc[a][b][cc] = 0.f;

            issue_loads(0, dynu, tid, m0, inpHi, inpLo, prvHi, prvLo, wHi, wLo);
            cp_commit();
            for (int c = 0; c < NCHUNK; c++) {
                if (c + 1 < NCHUNK) {
                    issue_loads(c + 1, dynu + ((c + 1) & 1) * BUFSZ, tid, m0,
                                inpHi, inpLo, prvHi, prvLo, wHi, wLo);
                    cp_commit();
                    cp_wait1();
                } else {
                    cp_wait0();
                }
                __syncthreads();
                compute_chunk(dynu + (c & 1) * BUFSZ, lane, wm, wn, acc);
                __syncthreads();
            }

            // ---- epilogue: bias + tanh + split/store -------------------------
            ush* hiBase = g_h_hi[l][t & 1];
            ush* loBase = g_h_lo[l][t & 1];
            float* ybase = out + (size_t)t * BH;
            float* hbase = out + (size_t)SS * BH + (size_t)l * BH;
            const bool wy = (l == LL - 1);
            const bool wh = (t == SS - 1);
            #pragma unroll
            for (int mb = 0; mb < 2; mb++) {
                #pragma unroll
                for (int rh = 0; rh < 2; rh++) {
                    const int gm = m0 + wm + mb * 16 + rh * 8 + (lane >> 2);
                    #pragma unroll
                    for (int nb = 0; nb < 4; nb++) {
                        const int cl = wn + nb * 8 + 2 * (lane & 3);   // 0..63
                        float p0 = acc[mb][nb][rh * 2 + 0] + s_bias[cl];
                        float p1 = acc[mb][nb][rh * 2 + 1] + s_bias[cl + 1];
                        float f0 = tanhf(p0);
                        float f1 = tanhf(p1);
                        ush h0v, l0v, h1v, l1v;
                        split2(f0, h0v, l0v);
                        split2(f1, h1v, l1v);
                        const size_t off = (size_t)gm * HH + n0 + cl;
                        *(unsigned*)(hiBase + off) = (unsigned)h0v | ((unsigned)h1v << 16);
                        *(unsigned*)(loBase + off) = (unsigned)l0v | ((unsigned)l1v << 16);
                        if (wy) *(float2*)(ybase + off) = make_float2(f0, f1);
                        if (wh) *(float2*)(hbase + off) = make_float2(f0, f1);
                    }
                }
            }
        }
        // cooperative split of x_{d+1} into the other ring slot
        const int tn = d + 1;
        if (tn < SS) {
            const int sl = tn & 1;
            for (int i = cta * NTHR + tid; i < BH; i += GSTRIDE)
                split2(x[(size_t)tn * BH + i], g_x_hi[sl][i], g_x_lo[sl][i]);
        }
        grid_barrier(bt++);
    }
}

extern "C" void kernel_launch(void* const* d_in, const int* in_sizes, int n_in,
                              void* d_out, int out_size) {
    const float* x    = (const float*)d_in[0];
    const float* h0   = (const float*)d_in[1];
    const float* W_ih = (const float*)d_in[2];
    const float* W_hh = (const float*)d_in[3];
    const float* b_ih = (const float*)d_in[4];
    const float* b_hh = (const float*)d_in[5];
    float* out = (float*)d_out;

    cudaFuncSetAttribute(rnn_mma, cudaFuncAttributeMaxDynamicSharedMemorySize, SMEM_DYN);
    void* sp = nullptr;
    cudaGetSymbolAddress(&sp, g_sync);
    cudaMemsetAsync(sp, 0, sizeof(unsigned) * 2);
    rnn_mma<<<NCTA, NTHR, SMEM_DYN>>>(x, h0, W_ih, W_hh, b_ih, b_hh, out);
}